// round 2
// baseline (speedup 1.0000x reference)
#include <cuda_runtime.h>

// LayerNormSoftmaxChain: x[N,4] -> LN(4) -> @W[4,3] -> softmax(3) -> out[N,3]
// N = 8388608. Pure HBM-streaming problem: 16B in / 12B out per row.
// Each thread handles 4 rows: 4x float4 loads, 3x float4 stores (vectorized
// despite the 12B/row output shape).

__global__ __launch_bounds__(256)
void lnsm_kernel(const float4* __restrict__ x4,
                 const float* __restrict__ W,      // [4,3] row-major
                 const float* __restrict__ gamma,  // [4]
                 const float* __restrict__ beta,   // [4]
                 float4* __restrict__ out4,        // viewing out[N,3] as float4[N*3/4]
                 int nquad)                        // nquad = N/4
{
    int i = blockIdx.x * blockDim.x + threadIdx.x;
    if (i >= nquad) return;

    // Tiny constants — L2/L1-resident after first wave.
    float w00 = __ldg(W + 0),  w01 = __ldg(W + 1),  w02 = __ldg(W + 2);
    float w10 = __ldg(W + 3),  w11 = __ldg(W + 4),  w12 = __ldg(W + 5);
    float w20 = __ldg(W + 6),  w21 = __ldg(W + 7),  w22 = __ldg(W + 8);
    float w30 = __ldg(W + 9),  w31 = __ldg(W + 10), w32 = __ldg(W + 11);
    float g0 = __ldg(gamma + 0), g1 = __ldg(gamma + 1),
          g2 = __ldg(gamma + 2), g3 = __ldg(gamma + 3);
    float b0 = __ldg(beta + 0), b1 = __ldg(beta + 1),
          b2 = __ldg(beta + 2), b3 = __ldg(beta + 3);

    // Front-batch the 4 row loads for MLP.
    float4 v0 = x4[(size_t)i * 4 + 0];
    float4 v1 = x4[(size_t)i * 4 + 1];
    float4 v2 = x4[(size_t)i * 4 + 2];
    float4 v3 = x4[(size_t)i * 4 + 3];

    float o[12];

    float4 vs[4] = {v0, v1, v2, v3};
    #pragma unroll
    for (int r = 0; r < 4; r++) {
        float4 v = vs[r];
        float mu  = (v.x + v.y + v.z + v.w) * 0.25f;
        float a = v.x - mu, b = v.y - mu, c = v.z - mu, d = v.w - mu;
        float var = (a * a + b * b + c * c + d * d) * 0.25f;
        float inv = rsqrtf(var + 1e-5f);

        float h0 = a * inv * g0 + b0;
        float h1 = b * inv * g1 + b1;
        float h2 = c * inv * g2 + b2;
        float h3 = d * inv * g3 + b3;

        // logits = h @ W  (W is [4,3] row-major)
        float l0 = h0 * w00 + h1 * w10 + h2 * w20 + h3 * w30;
        float l1 = h0 * w01 + h1 * w11 + h2 * w21 + h3 * w31;
        float l2 = h0 * w02 + h1 * w12 + h2 * w22 + h3 * w32;

        // softmax over 3
        float m  = fmaxf(l0, fmaxf(l1, l2));
        float e0 = __expf(l0 - m);
        float e1 = __expf(l1 - m);
        float e2 = __expf(l2 - m);
        float rs = 1.0f / (e0 + e1 + e2);

        o[r * 3 + 0] = e0 * rs;
        o[r * 3 + 1] = e1 * rs;
        o[r * 3 + 2] = e2 * rs;
    }

    // 12 contiguous floats -> 3 vectorized stores.
    out4[(size_t)i * 3 + 0] = make_float4(o[0], o[1], o[2],  o[3]);
    out4[(size_t)i * 3 + 1] = make_float4(o[4], o[5], o[6],  o[7]);
    out4[(size_t)i * 3 + 2] = make_float4(o[8], o[9], o[10], o[11]);
}

extern "C" void kernel_launch(void* const* d_in, const int* in_sizes, int n_in,
                              void* d_out, int out_size)
{
    const float* x     = (const float*)d_in[0];   // [N,4]
    const float* W     = (const float*)d_in[1];   // [4,3]
    const float* gamma = (const float*)d_in[2];   // [4]
    const float* beta  = (const float*)d_in[3];   // [4]
    float* out = (float*)d_out;                   // [N,3]

    int n_rows = in_sizes[0] / 4;
    int nquad  = n_rows / 4;                      // rows per thread = 4

    int threads = 256;
    int blocks  = (nquad + threads - 1) / threads;
    lnsm_kernel<<<blocks, threads>>>((const float4*)x, W, gamma, beta,
                                     (float4*)out, nquad);
}